// round 14
// baseline (speedup 1.0000x reference)
#include <cuda_runtime.h>
#include <cuda_fp16.h>
#include <cstdint>
#include <cstddef>

#define N_NODES 50000
#define N_EDGES 500000
#define D 128
#define H1 256
#define TABN 4097
#define TABPAD 4104

#define BK 32
#define ALD 36
#define BLD 36
#define STAGES 3
#define SMEM_BYTES (STAGES * (128 + 64) * 36 * 4)

// fp16 edge-kernel tile
#define E_ALD 40
#define E_ASZ (64 * E_ALD)
#define E_BSZ (128 * E_ALD)
#define E_STG (E_ASZ + E_BSZ)
#define SMEM2_BYTES (STAGES * E_STG * 2)

// ---------------- scratch ----------------
__device__ float d_h  [N_NODES * D];
__device__ float d_h2 [N_NODES * D];
__device__ float d_hr [N_NODES * D];
__device__ float d_nh [N_NODES * H1];
__device__ __half d_UVh[(size_t)N_NODES * 4 * H1]; // [50k,1024] fp16: UP|VP|UC|VC
__device__ float d_sp [N_NODES * D];
__device__ float d_sc [N_NODES * D];
__device__ float d_cp [N_NODES];
__device__ float d_cc [N_NODES];
__device__ float d_grid[TABPAD];
__device__ float d_epT [TABPAD * D];
__device__ float d_tabP[TABPAD * H1];
__device__ float d_tabC[TABPAD * H1];
// transposed + tf32-rounded weights ([N][K])
__device__ float d_wV1[D * H1];
__device__ float d_wV2[H1 * D];
__device__ float d_wE2[H1 * D];
__device__ float d_wUV[4 * H1 * D];
__device__ float d_wP1c[H1 * D];
__device__ float d_wC1c[H1 * D];
__device__ float d_wP2[H1 * D];
__device__ float d_wC2[H1 * D];
__device__ float d_wA1[3 * D * H1];
__device__ float d_wA2[H1 * D];
// fp16 transposed weights for edge layer-2 ([128][256])
__device__ __half d_wP2h[D * H1];
__device__ __half d_wC2h[D * H1];

// ---------------- helpers ----------------
__device__ __forceinline__ float tf32r(float v) {
    uint32_t r;
    asm("cvt.rna.tf32.f32 %0, %1;" : "=r"(r) : "f"(v));
    return __uint_as_float(r);
}

__device__ __forceinline__ float4 h4f(uint2 r) {
    __half2 a = *reinterpret_cast<__half2*>(&r.x);
    __half2 b = *reinterpret_cast<__half2*>(&r.y);
    float2 fa = __half22float2(a), fb = __half22float2(b);
    return make_float4(fa.x, fa.y, fb.x, fb.y);
}

__device__ __forceinline__ void u4tof(uint4 r, float* f) {
    float2 a = __half22float2(*reinterpret_cast<__half2*>(&r.x));
    float2 b = __half22float2(*reinterpret_cast<__half2*>(&r.y));
    float2 c = __half22float2(*reinterpret_cast<__half2*>(&r.z));
    float2 d = __half22float2(*reinterpret_cast<__half2*>(&r.w));
    f[0]=a.x; f[1]=a.y; f[2]=b.x; f[3]=b.y; f[4]=c.x; f[5]=c.y; f[6]=d.x; f[7]=d.y;
}
__device__ __forceinline__ uint4 ftou4(const float* f) {
    uint4 o;
    *reinterpret_cast<__half2*>(&o.x) = __floats2half2_rn(f[0], f[1]);
    *reinterpret_cast<__half2*>(&o.y) = __floats2half2_rn(f[2], f[3]);
    *reinterpret_cast<__half2*>(&o.z) = __floats2half2_rn(f[4], f[5]);
    *reinterpret_cast<__half2*>(&o.w) = __floats2half2_rn(f[6], f[7]);
    return o;
}

__device__ __forceinline__ void red_add2(float* p, float a, float b) {
    asm volatile("red.global.add.v2.f32 [%0], {%1, %2};"
                 :: "l"(p), "f"(a), "f"(b) : "memory");
}

__device__ __forceinline__ void mma_tf32(float c[4],
                                         uint32_t a0, uint32_t a1, uint32_t a2, uint32_t a3,
                                         uint32_t b0, uint32_t b1) {
    asm volatile(
        "mma.sync.aligned.m16n8k8.row.col.f32.tf32.tf32.f32 "
        "{%0,%1,%2,%3}, {%4,%5,%6,%7}, {%8,%9}, {%0,%1,%2,%3};"
        : "+f"(c[0]), "+f"(c[1]), "+f"(c[2]), "+f"(c[3])
        : "r"(a0), "r"(a1), "r"(a2), "r"(a3), "r"(b0), "r"(b1));
}

__device__ __forceinline__ void mma_f16(float c[4],
                                        uint32_t a0, uint32_t a1, uint32_t a2, uint32_t a3,
                                        uint32_t b0, uint32_t b1) {
    asm volatile(
        "mma.sync.aligned.m16n8k16.row.col.f32.f16.f16.f32 "
        "{%0,%1,%2,%3}, {%4,%5,%6,%7}, {%8,%9}, {%0,%1,%2,%3};"
        : "+f"(c[0]), "+f"(c[1]), "+f"(c[2]), "+f"(c[3])
        : "r"(a0), "r"(a1), "r"(a2), "r"(a3), "r"(b0), "r"(b1));
}

__device__ __forceinline__ void ldsm4(uint32_t& r0, uint32_t& r1, uint32_t& r2, uint32_t& r3,
                                      const void* p) {
    uint32_t a = (uint32_t)__cvta_generic_to_shared(p);
    asm volatile("ldmatrix.sync.aligned.m8n8.x4.shared.b16 {%0,%1,%2,%3}, [%4];"
                 : "=r"(r0), "=r"(r1), "=r"(r2), "=r"(r3) : "r"(a));
}

__device__ __forceinline__ void cp16(void* sm, const void* gm, bool pred) {
    uint32_t sa = (uint32_t)__cvta_generic_to_shared(sm);
    int sz = pred ? 16 : 0;
    asm volatile("cp.async.cg.shared.global [%0], [%1], 16, %2;\n"
                 :: "r"(sa), "l"(gm), "r"(sz));
}

// ================= fp16 edge layer-2 GEMM (64x128 tile, SUM3T + v2-red) =======
// out[sidx[r], :128] += relu( fp16(relu(s0[i0[r]] + s1[i1[r]] + lerp(tab, ind[r])))
//                             @ Wt^T + bias )
// Wt fp16 [128][256]; tab fp32 rows of 256, 4097 knots; s0/s1 fp16 stride s01s.
__global__ __launch_bounds__(256) void gemm_e2(
    const float* __restrict__ tab,
    const __half* __restrict__ s0, const int* __restrict__ i0,
    const __half* __restrict__ s1, const int* __restrict__ i1,
    const float* __restrict__ rk_ind,
    int M, int s01s,
    const __half* __restrict__ Wt,
    const float* __restrict__ bias,
    float* __restrict__ out,
    const int* __restrict__ sidx)
{
    extern __shared__ __half smem2[];

    const int tid  = threadIdx.x;
    const int lane = tid & 31;
    const int wid  = tid >> 5;
    const int wm   = (wid & 1) * 32;     // 2 warps along M
    const int wn   = (wid >> 1) * 32;    // 4 warps along N
    const int bm   = blockIdx.y * 64;

    const int arw = tid & 63;            // staged A row
    const int acq = (tid >> 6) * 8;      // half-offset in 32-half k-tile

    const int gr = bm + arw;
    const bool aval = gr < M;
    const int g = aval ? gr : 0;
    const int rr0 = i0[g];
    const int rr1 = i1[g];
    float x = (aval ? __ldg(rk_ind + g) : 0.f) * 4096.0f;
    int trow = (int)x;
    if (trow > 4095) trow = 4095;
    const float fr = x - (float)trow;

    float acc[2][4][4] = {};
    const int KT = 256 / BK;             // 8

#define ESTAGE(k0, buf)                                                          \
    do {                                                                         \
        __half* Ab = (buf);                                                      \
        __half* Bb = (buf) + E_ASZ;                                              \
        {                                                                        \
            uint4 ru = *(const uint4*)(s0 + (size_t)rr0 * s01s + (k0) + acq);    \
            uint4 rv = *(const uint4*)(s1 + (size_t)rr1 * s01s + (k0) + acq);    \
            const float* tb = tab + (size_t)trow * 256 + (k0) + acq;             \
            float u[8], v[8], t0[8], t1[8], o[8];                                \
            u4tof(ru, u); u4tof(rv, v);                                          \
            *(float4*)&t0[0] = *(const float4*)tb;                               \
            *(float4*)&t0[4] = *(const float4*)(tb + 4);                         \
            *(float4*)&t1[0] = *(const float4*)(tb + 256);                       \
            *(float4*)&t1[4] = *(const float4*)(tb + 260);                       \
            _Pragma("unroll")                                                    \
            for (int j = 0; j < 8; ++j)                                          \
                o[j] = fmaxf(u[j] + v[j] + t0[j] + fr * (t1[j] - t0[j]), 0.f);   \
            *(uint4*)&Ab[arw * E_ALD + acq] = ftou4(o);                          \
        }                                                                        \
        _Pragma("unroll")                                                        \
        for (int it = 0; it < 2; ++it) {                                         \
            int n = arw + it * 64;                                               \
            cp16(&Bb[n * E_ALD + acq], Wt + (size_t)n * 256 + (k0) + acq, true); \
        }                                                                        \
    } while (0)

    ESTAGE(0, smem2);
    asm volatile("cp.async.commit_group;\n" ::: "memory");
    ESTAGE(BK, smem2 + E_STG);
    asm volatile("cp.async.commit_group;\n" ::: "memory");

    const int a_row = wm + ((lane >> 3) & 1) * 8 + (lane & 7);
    const int a_col = (lane >> 4) * 8;
    const int b_row = wn + (lane >> 4) * 8 + (lane & 7);
    const int b_col = ((lane >> 3) & 1) * 8;

    for (int t = 0; t < KT; ++t) {
        asm volatile("cp.async.wait_group 1;\n" ::: "memory");
        __syncthreads();

        const __half* Ab = smem2 + (t % STAGES) * E_STG;
        const __half* Bb = Ab + E_ASZ;
#pragma unroll
        for (int ks = 0; ks < 2; ++ks) {
            const int k = ks * 16;
            uint32_t a[2][4], b[4][2];
#pragma unroll
            for (int mi = 0; mi < 2; ++mi)
                ldsm4(a[mi][0], a[mi][1], a[mi][2], a[mi][3],
                      &Ab[(a_row + mi * 16) * E_ALD + a_col + k]);
#pragma unroll
            for (int nip = 0; nip < 2; ++nip)
                ldsm4(b[nip * 2][0], b[nip * 2][1], b[nip * 2 + 1][0], b[nip * 2 + 1][1],
                      &Bb[(b_row + nip * 16) * E_ALD + b_col + k]);
#pragma unroll
            for (int ni = 0; ni < 4; ++ni)
#pragma unroll
                for (int mi = 0; mi < 2; ++mi)
                    mma_f16(acc[mi][ni], a[mi][0], a[mi][1], a[mi][2], a[mi][3],
                            b[ni][0], b[ni][1]);
        }
        __syncthreads();
        if (t + 2 < KT) ESTAGE((t + 2) * BK, smem2 + ((t + 2) % STAGES) * E_STG);
        asm volatile("cp.async.commit_group;\n" ::: "memory");
    }

    // epilogue: relu + vector-red scatter
#pragma unroll
    for (int mi = 0; mi < 2; ++mi) {
        int r0 = bm + wm + mi * 16 + (lane >> 2);
        int r1 = r0 + 8;
        long b0r = (r0 < M) ? (long)sidx[r0] : 0;
        long b1r = (r1 < M) ? (long)sidx[r1] : 0;
#pragma unroll
        for (int ni = 0; ni < 4; ++ni) {
            int c0 = wn + ni * 8 + (lane & 3) * 2;
            float bz0 = bias[c0], bz1 = bias[c0 + 1];
            if (r0 < M)
                red_add2(&out[b0r * D + c0],
                         fmaxf(acc[mi][ni][0] + bz0, 0.f),
                         fmaxf(acc[mi][ni][1] + bz1, 0.f));
            if (r1 < M)
                red_add2(&out[b1r * D + c0],
                         fmaxf(acc[mi][ni][2] + bz0, 0.f),
                         fmaxf(acc[mi][ni][3] + bz1, 0.f));
        }
    }
#undef ESTAGE
}

// ---------------- unified tf32 GEMM, templated block tile (unchanged R13) -----
template<int TBM, int TBN>
__global__ __launch_bounds__(256) void gemm_tc(
    const float* __restrict__ A,
    const float* __restrict__ s0, const int* __restrict__ i0,
    const float* __restrict__ s1, const int* __restrict__ i1,
    const float* __restrict__ s2,
    const float* __restrict__ rk_ind, const float* __restrict__ rk_w1,
    const float* __restrict__ rk_b1,
    int M, int K, int s01s,
    const float* __restrict__ Wt, int Nn,
    const float* __restrict__ bias,
    float* __restrict__ out,
    int loader, int mode, const int* __restrict__ sidx,
    const float* __restrict__ res,
    int round_out, float* __restrict__ out2)
{
    constexpr int AIT = TBM / 32;
    constexpr int BIT = TBN / 32;
    constexpr int ASZ = TBM * ALD;
    constexpr int BSZ = TBN * BLD;
    constexpr int STG = ASZ + BSZ;
    constexpr int WGM = TBM / 32;

    extern __shared__ float smem[];

    const int tid  = threadIdx.x;
    const int lane = tid & 31;
    const int wid  = tid >> 5;
    const int wm   = (wid % WGM) * 32;
    const int wn   = (wid / WGM) * 32;
    const int bm   = blockIdx.y * TBM;
    const int bn   = blockIdx.x * TBN;

    const int akq = (tid & 7) * 4;
    int arow[AIT]; bool aval[AIT]; int rr0[AIT], rr1[AIT], trow[AIT]; float aind[AIT];
#pragma unroll
    for (int it = 0; it < AIT; ++it) {
        int r  = it * 32 + (tid >> 3);
        int gr = bm + r;
        aval[it] = (gr < M);
        int g = aval[it] ? gr : 0;
        arow[it] = g;
        trow[it] = 0;
        if (loader == 1 || loader == 3) {
            rr0[it] = i0 ? i0[g] : g;
            rr1[it] = i1 ? i1[g] : g;
        }
        if (loader == 2) {
            aind[it] = aval[it] ? __ldg(rk_ind + g) : 0.f;
        } else if (loader == 3) {
            float x = (aval[it] ? __ldg(rk_ind + g) : 0.f) * 4096.0f;
            int tr = (int)x;
            if (tr > 4095) tr = 4095;
            trow[it] = tr;
            aind[it] = x - (float)tr;
        }
    }
    const int bkq = (tid & 7) * 4;
    const int bn0 = tid >> 3;

    float acc[2][4][4] = {};
    const int KT = K / BK;

#define STAGE(k0, buf)                                                           \
    do {                                                                         \
        float* Ab = (buf);                                                       \
        float* Bb = (buf) + ASZ;                                                 \
        if (loader == 2) {                                                       \
            float4 w  = *(const float4*)(rk_w1 + (k0) + akq);                    \
            float4 bb = *(const float4*)(rk_b1 + (k0) + akq);                    \
            _Pragma("unroll")                                                    \
            for (int it = 0; it < AIT; ++it) {                                   \
                int r = it * 32 + (tid >> 3);                                    \
                float4 v;                                                        \
                v.x = tf32r(fmaxf(fmaf(aind[it], w.x, bb.x), 0.f));              \
                v.y = tf32r(fmaxf(fmaf(aind[it], w.y, bb.y), 0.f));              \
                v.z = tf32r(fmaxf(fmaf(aind[it], w.z, bb.z), 0.f));              \
                v.w = tf32r(fmaxf(fmaf(aind[it], w.w, bb.w), 0.f));              \
                *(float4*)&Ab[r * ALD + akq] = v;                                \
            }                                                                    \
        } else if (loader == 3) {                                                \
            uint2 ru[AIT], rv[AIT]; float4 t0[AIT], t1[AIT];                     \
            const __half* h0 = (const __half*)s0;                                \
            const __half* h1 = (const __half*)s1;                                \
            _Pragma("unroll")                                                    \
            for (int it = 0; it < AIT; ++it)                                     \
                ru[it] = *(const uint2*)(h0 + (size_t)rr0[it] * s01s + (k0) + akq); \
            _Pragma("unroll")                                                    \
            for (int it = 0; it < AIT; ++it)                                     \
                rv[it] = *(const uint2*)(h1 + (size_t)rr1[it] * s01s + (k0) + akq); \
            _Pragma("unroll")                                                    \
            for (int it = 0; it < AIT; ++it) {                                   \
                const float* tb = A + (size_t)trow[it] * 256 + (k0) + akq;       \
                t0[it] = *(const float4*)tb;                                     \
                t1[it] = *(const float4*)(tb + 256);                             \
            }                                                                    \
            _Pragma("unroll")                                                    \
            for (int it = 0; it < AIT; ++it) {                                   \
                int r = it * 32 + (tid >> 3);                                    \
                float fr = aind[it];                                             \
                float4 u = h4f(ru[it]);                                          \
                float4 v = h4f(rv[it]);                                          \
                float4 o;                                                        \
                o.x = tf32r(fmaxf(u.x + v.x + t0[it].x + fr * (t1[it].x - t0[it].x), 0.f)); \
                o.y = tf32r(fmaxf(u.y + v.y + t0[it].y + fr * (t1[it].y - t0[it].y), 0.f)); \
                o.z = tf32r(fmaxf(u.z + v.z + t0[it].z + fr * (t1[it].z - t0[it].z), 0.f)); \
                o.w = tf32r(fmaxf(u.w + v.w + t0[it].w + fr * (t1[it].w - t0[it].w), 0.f)); \
                *(float4*)&Ab[r * ALD + akq] = o;                                \
            }                                                                    \
        } else {                                                                 \
            _Pragma("unroll")                                                    \
            for (int it = 0; it < AIT; ++it) {                                   \
                int r = it * 32 + (tid >> 3);                                    \
                const float* src;                                                \
                if (loader == 1) {                                               \
                    int seg  = (k0) >> 7;                                        \
                    int koff = ((k0) & 127) + akq;                               \
                    src = (seg == 0) ? s0 + (size_t)rr0[it] * 128 + koff         \
                        : (seg == 1) ? s1 + (size_t)rr1[it] * 128 + koff         \
                        :              s2 + (size_t)arow[it] * 128 + koff;       \
                } else {                                                         \
                    src = A + (size_t)arow[it] * K + (k0) + akq;                 \
                }                                                                \
                cp16(&Ab[r * ALD + akq], src, aval[it]);                         \
            }                                                                    \
        }                                                                        \
        _Pragma("unroll")                                                        \
        for (int it = 0; it < BIT; ++it) {                                       \
            int n = bn0 + it * 32;                                               \
            cp16(&Bb[n * BLD + bkq],                                             \
                 Wt + (size_t)(bn + n) * K + (k0) + bkq, true);                  \
        }                                                                        \
    } while (0)

    STAGE(0, smem);
    asm volatile("cp.async.commit_group;\n" ::: "memory");
    if (KT > 1) STAGE(BK, smem + STG);
    asm volatile("cp.async.commit_group;\n" ::: "memory");

    const int a_row = wm + ((lane >> 3) & 1) * 8 + (lane & 7);
    const int a_col = (lane >> 4) * 4;
    const int b_row = wn + (lane >> 4) * 8 + (lane & 7);
    const int b_col = ((lane >> 3) & 1) * 4;

    for (int t = 0; t < KT; ++t) {
        asm volatile("cp.async.wait_group 1;\n" ::: "memory");
        __syncthreads();

        const float* Ab = smem + (t % STAGES) * STG;
        const float* Bb = Ab + ASZ;
#pragma unroll
        for (int ks = 0; ks < 4; ++ks) {
            const int k = ks * 8;
            uint32_t a[2][4], b[4][2];
#pragma unroll
            for (int mi = 0; mi < 2; ++mi)
                ldsm4(a[mi][0], a[mi][1], a[mi][2], a[mi][3],
                      &Ab[(a_row + mi * 16) * ALD + a_col + k]);
#pragma unroll
            for (int nip = 0; nip < 2; ++nip)
                ldsm4(b[nip * 2][0], b[nip * 2][1], b[nip * 2 + 1][0], b[nip * 2 + 1][1],
                      &Bb[(b_row + nip * 16) * BLD + b_col + k]);
#pragma unroll
            for (int ni = 0; ni < 4; ++ni)
#pragma unroll
                for (int mi = 0; mi < 2; ++mi)
                    mma_tf32(acc[mi][ni], a[mi][0], a[mi][1], a[mi][2], a[mi][3],
                             b[ni][0], b[ni][1]);
        }
        __syncthreads();
        if (t + 2 < KT) STAGE((t + 2) * BK, smem + ((t + 2) % STAGES) * STG);
        asm volatile("cp.async.commit_group;\n" ::: "memory");
    }

    // ---------------- epilogue ----------------
#pragma unroll
    for (int mi = 0; mi < 2; ++mi) {
        int r0 = bm + wm + mi * 16 + (lane >> 2);
        int r1 = r0 + 8;
#pragma unroll
        for (int ni = 0; ni < 4; ++ni) {
            int c0 = bn + wn + ni * 8 + (lane & 3) * 2;
            int c1 = c0 + 1;
            float bz0 = bias ? bias[c0] : 0.f;
            float bz1 = bias ? bias[c1] : 0.f;
            float raw00 = acc[mi][ni][0] + bz0;
            float raw01 = acc[mi][ni][1] + bz1;
            float raw10 = acc[mi][ni][2] + bz0;
            float raw11 = acc[mi][ni][3] + bz1;
            if (mode == 4) {
                __half* oh = (__half*)out;
                if (r0 < M)
                    *(__half2*)(oh + (size_t)r0 * Nn + c0) = __floats2half2_rn(raw00, raw01);
                if (r1 < M)
                    *(__half2*)(oh + (size_t)r1 * Nn + c0) = __floats2half2_rn(raw10, raw11);
                continue;
            }
            if (mode == 3) {
                if (r0 < M) {
                    out[(size_t)r0 * Nn + c0] = raw00;
                    out[(size_t)r0 * Nn + c1] = raw01;
                }
                if (r1 < M) {
                    out[(size_t)r1 * Nn + c0] = raw10;
                    out[(size_t)r1 * Nn + c1] = raw11;
                }
                continue;
            }
            float v00 = fmaxf(raw00, 0.f);
            float v01 = fmaxf(raw01, 0.f);
            float v10 = fmaxf(raw10, 0.f);
            float v11 = fmaxf(raw11, 0.f);
            if (mode == 0) {
                float w00 = round_out ? tf32r(v00) : v00;
                float w01 = round_out ? tf32r(v01) : v01;
                float w10 = round_out ? tf32r(v10) : v10;
                float w11 = round_out ? tf32r(v11) : v11;
                if (r0 < M) {
                    out[(size_t)r0 * Nn + c0] = w00;
                    out[(size_t)r0 * Nn + c1] = w01;
                    if (out2) {
                        out2[(size_t)r0 * Nn + c0] = tf32r(v00);
                        out2[(size_t)r0 * Nn + c1] = tf32r(v01);
                    }
                }
                if (r1 < M) {
                    out[(size_t)r1 * Nn + c0] = w10;
                    out[(size_t)r1 * Nn + c1] = w11;
                    if (out2) {
                        out2[(size_t)r1 * Nn + c0] = tf32r(v10);
                        out2[(size_t)r1 * Nn + c1] = tf32r(v11);
                    }
                }
            } else if (mode == 1) {
                if (r0 < M) {
                    size_t b = (size_t)sidx[r0] * Nn;
                    red_add2(&out[b + c0], v00, v01);
                }
                if (r1 < M) {
                    size_t b = (size_t)sidx[r1] * Nn;
                    red_add2(&out[b + c0], v10, v11);
                }
            } else {
                if (r0 < M) {
                    size_t b = (size_t)r0 * Nn;
                    float w0 = fmaxf(res[b + c0] + v00, 0.f);
                    float w1 = fmaxf(res[b + c1] + v01, 0.f);
                    out[b + c0] = w0; out[b + c1] = w1;
                    if (out2) { out2[b + c0] = tf32r(w0); out2[b + c1] = tf32r(w1); }
                }
                if (r1 < M) {
                    size_t b = (size_t)r1 * Nn;
                    float w0 = fmaxf(res[b + c0] + v10, 0.f);
                    float w1 = fmaxf(res[b + c1] + v11, 0.f);
                    out[b + c0] = w0; out[b + c1] = w1;
                    if (out2) { out2[b + c0] = tf32r(w0); out2[b + c1] = tf32r(w1); }
                }
            }
        }
    }
#undef STAGE
}

// ---------------- small kernels ----------------
__global__ void count_edges(const int* __restrict__ pn, const int* __restrict__ cn,
                            float* __restrict__ cp, float* __restrict__ cc)
{
    int e = blockIdx.x * blockDim.x + threadIdx.x;
    if (e < N_EDGES) {
        atomicAdd(&cp[pn[e]], 1.f);
        atomicAdd(&cc[cn[e]], 1.f);
    }
}

__global__ void finalize_s(float* __restrict__ sp, float* __restrict__ sc,
                           const float* __restrict__ cp, const float* __restrict__ cc,
                           const float* __restrict__ pm, const float* __restrict__ cm,
                           const float* __restrict__ st, const float* __restrict__ et)
{
    int i = blockIdx.x * blockDim.x + threadIdx.x;
    if (i >= N_NODES * D) return;
    int n = i >> 7, d = i & 127;
    sp[i] = tf32r(sp[i] / fmaxf(cp[n], 1.f) + pm[n] * st[d]);
    sc[i] = tf32r(sc[i] / fmaxf(cc[n], 1.f) + cm[n] * et[d]);
}

__global__ void round_copy(const float* __restrict__ in, float* __restrict__ o, int n)
{
    int i = blockIdx.x * blockDim.x + threadIdx.x;
    if (i < n) o[i] = tf32r(in[i]);
}

__global__ void fill_grid(float* __restrict__ g)
{
    int i = blockIdx.x * blockDim.x + threadIdx.x;
    if (i < TABPAD) {
        int j = i > 4096 ? 4096 : i;
        g[i] = (float)j * (1.0f / 4096.0f);
    }
}

__global__ void transpose_round(const float* __restrict__ src, float* __restrict__ dst,
                                int K, int N)
{
    int i = blockIdx.x * blockDim.x + threadIdx.x;
    if (i >= K * N) return;
    int k = i / N, n = i % N;
    dst[(size_t)n * K + k] = tf32r(src[i]);
}

__global__ void transpose_half(const float* __restrict__ src, __half* __restrict__ dst,
                               int K, int N)
{
    int i = blockIdx.x * blockDim.x + threadIdx.x;
    if (i >= K * N) return;
    int k = i / N, n = i % N;
    dst[(size_t)n * K + k] = __float2half_rn(src[i]);
}

// ---------------- host ----------------
extern "C" void kernel_launch(void* const* d_in, const int* in_sizes, int n_in,
                              void* d_out, int out_size)
{
    (void)in_sizes; (void)n_in; (void)out_size;
    const float* batch_token = (const float*)d_in[0];
    const int*   e_p_node    = (const int*)  d_in[1];
    const int*   e_c_node    = (const int*)  d_in[2];
    const float* e_p_ind     = (const float*)d_in[3];
    const float* e_c_ind     = (const float*)d_in[4];
    const float* p_mask      = (const float*)d_in[5];
    const float* c_mask      = (const float*)d_in[6];
    const float* start_tok   = (const float*)d_in[7];
    const float* end_tok     = (const float*)d_in[8];
    const float* Wt[20];
    for (int i = 0; i < 20; i++) Wt[i] = (const float*)d_in[9 + i];
    const float *Vw1=Wt[0],*Vb1=Wt[1],*Vw2=Wt[2],*Vb2=Wt[3];
    const float *Ew1=Wt[4],*Eb1=Wt[5],*Ew2=Wt[6],*Eb2=Wt[7];
    const float *Pw1=Wt[8],*Pb1=Wt[9],*Pw2=Wt[10],*Pb2=Wt[11];
    const float *Cw1=Wt[12],*Cb1=Wt[13],*Cw2=Wt[14],*Cb2=Wt[15];
    const float *Aw1=Wt[16],*Ab1=Wt[17],*Aw2=Wt[18],*Ab2=Wt[19];

    float *g_h, *g_h2, *g_hr, *g_nh, *g_sp, *g_sc, *g_cp, *g_cc;
    float *g_grid, *g_epT, *g_tabP, *g_tabC;
    __half *g_UVh, *w_P2h, *w_C2h;
    float *w_V1, *w_V2, *w_E2, *w_UV, *w_P1c, *w_C1c, *w_P2, *w_C2, *w_A1, *w_A2;
    cudaGetSymbolAddress((void**)&g_h,    d_h);
    cudaGetSymbolAddress((void**)&g_h2,   d_h2);
    cudaGetSymbolAddress((void**)&g_hr,   d_hr);
    cudaGetSymbolAddress((void**)&g_nh,   d_nh);
    cudaGetSymbolAddress((void**)&g_UVh,  d_UVh);
    cudaGetSymbolAddress((void**)&g_sp,   d_sp);
    cudaGetSymbolAddress((void**)&g_sc,   d_sc);
    cudaGetSymbolAddress((void**)&g_cp,   d_cp);
    cudaGetSymbolAddress((void**)&g_cc,   d_cc);
    cudaGetSymbolAddress((void**)&g_grid, d_grid);
    cudaGetSymbolAddress((void**)&g_epT,  d_epT);
    cudaGetSymbolAddress((void**)&g_tabP, d_tabP);
    cudaGetSymbolAddress((void**)&g_tabC, d_tabC);
    cudaGetSymbolAddress((void**)&w_V1,   d_wV1);
    cudaGetSymbolAddress((void**)&w_V2,   d_wV2);
    cudaGetSymbolAddress((void**)&w_E2,   d_wE2);
    cudaGetSymbolAddress((void**)&w_UV,   d_wUV);
    cudaGetSymbolAddress((void**)&w_P1c,  d_wP1c);
    cudaGetSymbolAddress((void**)&w_C1c,  d_wC1c);
    cudaGetSymbolAddress((void**)&w_P2,   d_wP2);
    cudaGetSymbolAddress((void**)&w_C2,   d_wC2);
    cudaGetSymbolAddress((void**)&w_A1,   d_wA1);
    cudaGetSymbolAddress((void**)&w_A2,   d_wA2);
    cudaGetSymbolAddress((void**)&w_P2h,  d_wP2h);
    cudaGetSymbolAddress((void**)&w_C2h,  d_wC2h);

    cudaFuncSetAttribute(gemm_tc<128, 64>, cudaFuncAttributeMaxDynamicSharedMemorySize, SMEM_BYTES);
    cudaFuncSetAttribute(gemm_tc<64, 128>, cudaFuncAttributeMaxDynamicSharedMemorySize, SMEM_BYTES);
    cudaFuncSetAttribute(gemm_e2, cudaFuncAttributeMaxDynamicSharedMemorySize, SMEM2_BYTES);

    cudaStream_t s = 0;
    const size_t SB = SMEM_BYTES;

    auto tr = [&](const float* src, float* dst, int K, int N) {
        transpose_round<<<(K * N + 255) / 256, 256, 0, s>>>(src, dst, K, N);
    };
    tr(Vw1, w_V1, D, H1);   tr(Vw2, w_V2, H1, D);   tr(Ew2, w_E2, H1, D);
    tr(Pw1,              w_UV + 0 * H1 * D, D, H1);
    tr(Pw1 + D * H1,     w_UV + 1 * H1 * D, D, H1);
    tr(Cw1,              w_UV + 2 * H1 * D, D, H1);
    tr(Cw1 + D * H1,     w_UV + 3 * H1 * D, D, H1);
    tr(Pw1 + 2 * D * H1, w_P1c, D, H1);
    tr(Cw1 + 2 * D * H1, w_C1c, D, H1);
    tr(Pw2, w_P2, H1, D);   tr(Cw2, w_C2, H1, D);
    tr(Aw1, w_A1, 3 * D, H1);   tr(Aw2, w_A2, H1, D);
    transpose_half<<<(H1 * D + 255) / 256, 256, 0, s>>>(Pw2, w_P2h, H1, D);
    transpose_half<<<(H1 * D + 255) / 256, 256, 0, s>>>(Cw2, w_C2h, H1, D);
    round_copy<<<(N_NODES * D + 255) / 256, 256, 0, s>>>(batch_token, g_hr, N_NODES * D);
    fill_grid<<<(TABPAD + 255) / 256, 256, 0, s>>>(g_grid);

    cudaMemsetAsync(g_cp, 0, N_NODES * sizeof(float), s);
    cudaMemsetAsync(g_cc, 0, N_NODES * sizeof(float), s);
    count_edges<<<(N_EDGES + 255) / 256, 256, 0, s>>>(e_p_node, e_c_node, g_cp, g_cc);

#define GEMM_A(Aptr, S0, I0, S1, I1, S2, RKI, RKW, RKB, M_, K_, S01S, WT, NN, BIAS, OUT, LD, MD, SIDX, RES, RO, OUT2) \
    gemm_tc<128, 64><<<dim3((NN) / 64, ((M_) + 127) / 128), 256, SB, s>>>(Aptr, S0, I0, S1, I1, S2, \
        RKI, RKW, RKB, M_, K_, S01S, WT, NN, BIAS, OUT, LD, MD, SIDX, RES, RO, OUT2)

    // ---- h0 = MLP_V(batch_token_rounded) ----
    GEMM_A(g_hr, nullptr,nullptr,nullptr,nullptr,nullptr, nullptr,nullptr,nullptr,
           N_NODES, D, 0, w_V1, H1, Vb1, g_nh, 0, 0, nullptr, nullptr, 1, nullptr);
    GEMM_A(g_nh, nullptr,nullptr,nullptr,nullptr,nullptr, nullptr,nullptr,nullptr,
           N_NODES, H1, 0, w_V2, D, Vb2, g_h, 0, 0, nullptr, nullptr, 0, g_hr);

    // ---- edge-MLP lookup tables on 4097 knots ----
    GEMM_A(nullptr, nullptr,nullptr,nullptr,nullptr,nullptr, g_grid, Ew1, Eb1,
           TABN, H1, 0, w_E2, D, Eb2, g_epT, 2, 0, nullptr, nullptr, 1, nullptr);
    GEMM_A(g_epT, nullptr,nullptr,nullptr,nullptr,nullptr, nullptr,nullptr,nullptr,
           TABN, D, 0, w_P1c, H1, Pb1, g_tabP, 0, 3, nullptr, nullptr, 0, nullptr);
    GEMM_A(g_epT, nullptr,nullptr,nullptr,nullptr,nullptr, nullptr,nullptr,nullptr,
           TABN, D, 0, w_C1c, H1, Cb1, g_tabC, 0, 3, nullptr, nullptr, 0, nullptr);

    // ---- hops ----
    float* hin  = g_h;
    float* hout = g_h2;
    for (int hop = 0; hop < 3; hop++) {
        cudaMemsetAsync(g_sp, 0, (size_t)N_NODES * D * sizeof(float), s);
        cudaMemsetAsync(g_sc, 0, (size_t)N_NODES * D * sizeof(float), s);

        // UV = h @ [P1a|P1b|C1a|C1b] -> [50k, 1024] fp16
        GEMM_A(g_hr, nullptr,nullptr,nullptr,nullptr,nullptr, nullptr,nullptr,nullptr,
               N_NODES, D, 0, w_UV, 4 * H1, nullptr, (float*)g_UVh, 0, 4, nullptr, nullptr, 0, nullptr);

        // P layer2 (fp16 MMA, v2-red scatter)
        gemm_e2<<<dim3(1, (N_EDGES + 63) / 64), 256, SMEM2_BYTES, s>>>(
            g_tabP, g_UVh + 0, e_c_node, g_UVh + H1, e_p_node, e_p_ind,
            N_EDGES, 4 * H1, w_P2h, Pb2, g_sp, e_p_node);

        // C layer2
        gemm_e2<<<dim3(1, (N_EDGES + 63) / 64), 256, SMEM2_BYTES, s>>>(
            g_tabC, g_UVh + 2 * H1, e_p_node, g_UVh + 3 * H1, e_c_node, e_c_ind,
            N_EDGES, 4 * H1, w_C2h, Cb2, g_sc, e_c_node);

        finalize_s<<<(N_NODES * D + 255) / 256, 256, 0, s>>>(
            g_sp, g_sc, g_cp, g_cc, p_mask, c_mask, start_tok, end_tok);

        // aggregator
        GEMM_A(nullptr, g_hr, nullptr, g_sp, nullptr, g_sc, nullptr,nullptr,nullptr,
               N_NODES, 3 * D, 0, w_A1, H1, Ab1, g_nh, 1, 0, nullptr, nullptr, 1, nullptr);
        float* hdst = (hop == 2) ? (float*)d_out : hout;
        GEMM_A(g_nh, nullptr,nullptr,nullptr,nullptr,nullptr, nullptr,nullptr,nullptr,
               N_NODES, H1, 0, w_A2, D, Ab2, hdst, 0, 2, nullptr, hin, 0, g_hr);

        float* tmp = hin;
        hin  = hdst;
        hout = tmp;
    }
#undef GEMM_A
}

// round 15
// speedup vs baseline: 1.2024x; 1.2024x over previous
#include <cuda_runtime.h>
#include <cuda_fp16.h>
#include <cstdint>
#include <cstddef>

#define N_NODES 50000
#define N_EDGES 500000
#define D 128
#define H1 256
#define TABN 4097
#define TABPAD 4104

#define BK 32
#define ALD 36
#define BLD 36
#define STAGES 3
#define SMEM_BYTES (STAGES * (128 + 64) * 36 * 4)

// ---------------- scratch ----------------
__device__ float d_h  [N_NODES * D];
__device__ float d_h2 [N_NODES * D];
__device__ float d_hr [N_NODES * D];
__device__ float d_nh [N_NODES * H1];
__device__ __half d_UVh[(size_t)N_NODES * 4 * H1]; // [50k,1024] fp16: UP|VP|UC|VC
__device__ float d_spc[2 * N_NODES * D];           // sp | sc contiguous
__device__ float d_cpc[2 * N_NODES];               // cp | cc
__device__ float d_icpc[2 * N_NODES];              // 1/max(cp,1) | 1/max(cc,1)
__device__ float d_grid[TABPAD];
__device__ float d_epT [TABPAD * D];
__device__ float d_tabP[TABPAD * H1];
__device__ float d_tabC[TABPAD * H1];
// transposed + tf32-rounded weights ([N][K])
__device__ float d_wV1[D * H1];
__device__ float d_wV2[H1 * D];
__device__ float d_wE2[H1 * D];
__device__ float d_wUV[4 * H1 * D];
__device__ float d_wP1c[H1 * D];
__device__ float d_wC1c[H1 * D];
__device__ float d_wP2[H1 * D];
__device__ float d_wC2[H1 * D];
__device__ float d_wA1[3 * D * H1];
__device__ float d_wA2[H1 * D];

// ---------------- helpers ----------------
__device__ __forceinline__ float tf32r(float v) {
    uint32_t r;
    asm("cvt.rna.tf32.f32 %0, %1;" : "=r"(r) : "f"(v));
    return __uint_as_float(r);
}

__device__ __forceinline__ float4 h4f(uint2 r) {
    __half2 a = *reinterpret_cast<__half2*>(&r.x);
    __half2 b = *reinterpret_cast<__half2*>(&r.y);
    float2 fa = __half22float2(a), fb = __half22float2(b);
    return make_float4(fa.x, fa.y, fb.x, fb.y);
}

__device__ __forceinline__ void red_add2(float* p, float a, float b) {
    asm volatile("red.global.add.v2.f32 [%0], {%1, %2};"
                 :: "l"(p), "f"(a), "f"(b) : "memory");
}

__device__ __forceinline__ void mma_tf32(float c[4],
                                         uint32_t a0, uint32_t a1, uint32_t a2, uint32_t a3,
                                         uint32_t b0, uint32_t b1) {
    asm volatile(
        "mma.sync.aligned.m16n8k8.row.col.f32.tf32.tf32.f32 "
        "{%0,%1,%2,%3}, {%4,%5,%6,%7}, {%8,%9}, {%0,%1,%2,%3};"
        : "+f"(c[0]), "+f"(c[1]), "+f"(c[2]), "+f"(c[3])
        : "r"(a0), "r"(a1), "r"(a2), "r"(a3), "r"(b0), "r"(b1));
}

__device__ __forceinline__ void ldsm4(uint32_t& r0, uint32_t& r1, uint32_t& r2, uint32_t& r3,
                                      const float* p) {
    uint32_t a = (uint32_t)__cvta_generic_to_shared(p);
    asm volatile("ldmatrix.sync.aligned.m8n8.x4.shared.b16 {%0,%1,%2,%3}, [%4];"
                 : "=r"(r0), "=r"(r1), "=r"(r2), "=r"(r3) : "r"(a));
}

__device__ __forceinline__ void cp16(float* sm, const float* gm, bool pred) {
    uint32_t sa = (uint32_t)__cvta_generic_to_shared(sm);
    int sz = pred ? 16 : 0;
    asm volatile("cp.async.cg.shared.global [%0], [%1], 16, %2;\n"
                 :: "r"(sa), "l"(gm), "r"(sz));
}

// ---------------- unified tf32 GEMM, templated block tile ----------------
// <TBM, TBN> in {<128,64>, <64,128>}; 256 threads; warp tile 32x32.
// Wt is TRANSPOSED-ROUNDED [Nn][K].
// loader: 0 DIRECT, 1 CAT3(K=384), 2 RANK1, 3 SUM3T (fp16 gathers + fp32 lerp table),
//         4 AGG (K=384: seg0 = hr row; seg1 = rnd(sp*icp + pm*st); seg2 = rnd(sc*icc + cm*et))
//             s0=hr, s1=sp, s2=sc, rk_ind=inv_cp, rk_w1=start_tok, rk_b1=end_tok,
//             aux_pm=p_mask, aux_cm=c_mask, aux_icc=inv_cc
// mode: 0 relu-store(+round/out2), 1 vector-red scatter relu, 2 residual,
//       3 raw fp32 store, 4 raw fp16 store
template<int TBM, int TBN>
__global__ __launch_bounds__(256) void gemm_tc(
    const float* __restrict__ A,
    const float* __restrict__ s0, const int* __restrict__ i0,
    const float* __restrict__ s1, const int* __restrict__ i1,
    const float* __restrict__ s2,
    const float* __restrict__ rk_ind, const float* __restrict__ rk_w1,
    const float* __restrict__ rk_b1,
    int M, int K, int s01s,
    const float* __restrict__ Wt, int Nn,
    const float* __restrict__ bias,
    float* __restrict__ out,
    int loader, int mode, const int* __restrict__ sidx,
    const float* __restrict__ res,
    int round_out, float* __restrict__ out2,
    const float* __restrict__ aux_pm, const float* __restrict__ aux_cm,
    const float* __restrict__ aux_icc)
{
    constexpr int AIT = TBM / 32;
    constexpr int BIT = TBN / 32;
    constexpr int ASZ = TBM * ALD;
    constexpr int BSZ = TBN * BLD;
    constexpr int STG = ASZ + BSZ;
    constexpr int WGM = TBM / 32;

    extern __shared__ float smem[];

    const int tid  = threadIdx.x;
    const int lane = tid & 31;
    const int wid  = tid >> 5;
    const int wm   = (wid % WGM) * 32;
    const int wn   = (wid / WGM) * 32;
    const int bm   = blockIdx.y * TBM;
    const int bn   = blockIdx.x * TBN;

    const int akq = (tid & 7) * 4;
    int arow[AIT]; bool aval[AIT]; int rr0[AIT], rr1[AIT], trow[AIT];
    float aind[AIT], pmv[AIT], iccv[AIT], cmv[AIT];
#pragma unroll
    for (int it = 0; it < AIT; ++it) {
        int r  = it * 32 + (tid >> 3);
        int gr = bm + r;
        aval[it] = (gr < M);
        int g = aval[it] ? gr : 0;
        arow[it] = g;
        trow[it] = 0;
        if (loader == 1 || loader == 3) {
            rr0[it] = i0 ? i0[g] : g;
            rr1[it] = i1 ? i1[g] : g;
        }
        if (loader == 2) {
            aind[it] = aval[it] ? __ldg(rk_ind + g) : 0.f;
        } else if (loader == 3) {
            float x = (aval[it] ? __ldg(rk_ind + g) : 0.f) * 4096.0f;
            int tr = (int)x;
            if (tr > 4095) tr = 4095;
            trow[it] = tr;
            aind[it] = x - (float)tr;
        } else if (loader == 4) {
            aind[it] = __ldg(rk_ind + g);    // inv_cp
            pmv[it]  = __ldg(aux_pm + g);
            iccv[it] = __ldg(aux_icc + g);   // inv_cc
            cmv[it]  = __ldg(aux_cm + g);
        }
    }
    const int bkq = (tid & 7) * 4;
    const int bn0 = tid >> 3;

    float acc[2][4][4] = {};
    const int KT = K / BK;

#define STAGE(k0, buf)                                                           \
    do {                                                                         \
        float* Ab = (buf);                                                       \
        float* Bb = (buf) + ASZ;                                                 \
        if (loader == 2) {                                                       \
            float4 w  = *(const float4*)(rk_w1 + (k0) + akq);                    \
            float4 bb = *(const float4*)(rk_b1 + (k0) + akq);                    \
            _Pragma("unroll")                                                    \
            for (int it = 0; it < AIT; ++it) {                                   \
                int r = it * 32 + (tid >> 3);                                    \
                float4 v;                                                        \
                v.x = tf32r(fmaxf(fmaf(aind[it], w.x, bb.x), 0.f));              \
                v.y = tf32r(fmaxf(fmaf(aind[it], w.y, bb.y), 0.f));              \
                v.z = tf32r(fmaxf(fmaf(aind[it], w.z, bb.z), 0.f));              \
                v.w = tf32r(fmaxf(fmaf(aind[it], w.w, bb.w), 0.f));              \
                *(float4*)&Ab[r * ALD + akq] = v;                                \
            }                                                                    \
        } else if (loader == 3) {                                                \
            uint2 ru[AIT], rv[AIT]; float4 t0[AIT], t1[AIT];                     \
            const __half* h0 = (const __half*)s0;                                \
            const __half* h1 = (const __half*)s1;                                \
            _Pragma("unroll")                                                    \
            for (int it = 0; it < AIT; ++it)                                     \
                ru[it] = *(const uint2*)(h0 + (size_t)rr0[it] * s01s + (k0) + akq); \
            _Pragma("unroll")                                                    \
            for (int it = 0; it < AIT; ++it)                                     \
                rv[it] = *(const uint2*)(h1 + (size_t)rr1[it] * s01s + (k0) + akq); \
            _Pragma("unroll")                                                    \
            for (int it = 0; it < AIT; ++it) {                                   \
                const float* tb = A + (size_t)trow[it] * 256 + (k0) + akq;       \
                t0[it] = *(const float4*)tb;                                     \
                t1[it] = *(const float4*)(tb + 256);                             \
            }                                                                    \
            _Pragma("unroll")                                                    \
            for (int it = 0; it < AIT; ++it) {                                   \
                int r = it * 32 + (tid >> 3);                                    \
                float fr = aind[it];                                             \
                float4 u = h4f(ru[it]);                                          \
                float4 v = h4f(rv[it]);                                          \
                float4 o;                                                        \
                o.x = tf32r(fmaxf(u.x + v.x + t0[it].x + fr * (t1[it].x - t0[it].x), 0.f)); \
                o.y = tf32r(fmaxf(u.y + v.y + t0[it].y + fr * (t1[it].y - t0[it].y), 0.f)); \
                o.z = tf32r(fmaxf(u.z + v.z + t0[it].z + fr * (t1[it].z - t0[it].z), 0.f)); \
                o.w = tf32r(fmaxf(u.w + v.w + t0[it].w + fr * (t1[it].w - t0[it].w), 0.f)); \
                *(float4*)&Ab[r * ALD + akq] = o;                                \
            }                                                                    \
        } else if (loader == 4) {                                                \
            int seg  = (k0) >> 7;                                                \
            int koff = ((k0) & 127) + akq;                                       \
            if (seg == 0) {                                                      \
                _Pragma("unroll")                                                \
                for (int it = 0; it < AIT; ++it)                                 \
                    cp16(&Ab[(it * 32 + (tid >> 3)) * ALD + akq],                \
                         s0 + (size_t)arow[it] * 128 + koff, aval[it]);          \
            } else {                                                             \
                const float* base = (seg == 1) ? s1 : s2;                        \
                float4 tk = *(const float4*)(((seg == 1) ? rk_w1 : rk_b1) + koff); \
                _Pragma("unroll")                                                \
                for (int it = 0; it < AIT; ++it) {                               \
                    float4 v = *(const float4*)(base + (size_t)arow[it] * 128 + koff); \
                    float ic = (seg == 1) ? aind[it] : iccv[it];                 \
                    float mk = (seg == 1) ? pmv[it]  : cmv[it];                  \
                    int r = it * 32 + (tid >> 3);                                \
                    float4 o;                                                    \
                    o.x = tf32r(fmaf(v.x, ic, mk * tk.x));                       \
                    o.y = tf32r(fmaf(v.y, ic, mk * tk.y));                       \
                    o.z = tf32r(fmaf(v.z, ic, mk * tk.z));                       \
                    o.w = tf32r(fmaf(v.w, ic, mk * tk.w));                       \
                    *(float4*)&Ab[r * ALD + akq] = o;                            \
                }                                                                \
            }                                                                    \
        } else {                                                                 \
            _Pragma("unroll")                                                    \
            for (int it = 0; it < AIT; ++it) {                                   \
                int r = it * 32 + (tid >> 3);                                    \
                const float* src;                                                \
                if (loader == 1) {                                               \
                    int seg  = (k0) >> 7;                                        \
                    int koff = ((k0) & 127) + akq;                               \
                    src = (seg == 0) ? s0 + (size_t)rr0[it] * 128 + koff         \
                        : (seg == 1) ? s1 + (size_t)rr1[it] * 128 + koff         \
                        :              s2 + (size_t)arow[it] * 128 + koff;       \
                } else {                                                         \
                    src = A + (size_t)arow[it] * K + (k0) + akq;                 \
                }                                                                \
                cp16(&Ab[r * ALD + akq], src, aval[it]);                         \
            }                                                                    \
        }                                                                        \
        _Pragma("unroll")                                                        \
        for (int it = 0; it < BIT; ++it) {                                       \
            int n = bn0 + it * 32;                                               \
            cp16(&Bb[n * BLD + bkq],                                             \
                 Wt + (size_t)(bn + n) * K + (k0) + bkq, true);                  \
        }                                                                        \
    } while (0)

    STAGE(0, smem);
    asm volatile("cp.async.commit_group;\n" ::: "memory");
    if (KT > 1) STAGE(BK, smem + STG);
    asm volatile("cp.async.commit_group;\n" ::: "memory");

    const int a_row = wm + ((lane >> 3) & 1) * 8 + (lane & 7);
    const int a_col = (lane >> 4) * 4;
    const int b_row = wn + (lane >> 4) * 8 + (lane & 7);
    const int b_col = ((lane >> 3) & 1) * 4;

    for (int t = 0; t < KT; ++t) {
        asm volatile("cp.async.wait_group 1;\n" ::: "memory");
        __syncthreads();

        const float* Ab = smem + (t % STAGES) * STG;
        const float* Bb = Ab + ASZ;
#pragma unroll
        for (int ks = 0; ks < 4; ++ks) {
            const int k = ks * 8;
            uint32_t a[2][4], b[4][2];
#pragma unroll
            for (int mi = 0; mi < 2; ++mi)
                ldsm4(a[mi][0], a[mi][1], a[mi][2], a[mi][3],
                      &Ab[(a_row + mi * 16) * ALD + a_col + k]);
#pragma unroll
            for (int nip = 0; nip < 2; ++nip)
                ldsm4(b[nip * 2][0], b[nip * 2][1], b[nip * 2 + 1][0], b[nip * 2 + 1][1],
                      &Bb[(b_row + nip * 16) * BLD + b_col + k]);
#pragma unroll
            for (int ni = 0; ni < 4; ++ni)
#pragma unroll
                for (int mi = 0; mi < 2; ++mi)
                    mma_tf32(acc[mi][ni], a[mi][0], a[mi][1], a[mi][2], a[mi][3],
                             b[ni][0], b[ni][1]);
        }
        __syncthreads();
        if (t + 2 < KT) STAGE((t + 2) * BK, smem + ((t + 2) % STAGES) * STG);
        asm volatile("cp.async.commit_group;\n" ::: "memory");
    }

    // ---------------- epilogue (warp tile 32x32) ----------------
#pragma unroll
    for (int mi = 0; mi < 2; ++mi) {
        int r0 = bm + wm + mi * 16 + (lane >> 2);
        int r1 = r0 + 8;
#pragma unroll
        for (int ni = 0; ni < 4; ++ni) {
            int c0 = bn + wn + ni * 8 + (lane & 3) * 2;
            int c1 = c0 + 1;
            float bz0 = bias ? bias[c0] : 0.f;
            float bz1 = bias ? bias[c1] : 0.f;
            float raw00 = acc[mi][ni][0] + bz0;
            float raw01 = acc[mi][ni][1] + bz1;
            float raw10 = acc[mi][ni][2] + bz0;
            float raw11 = acc[mi][ni][3] + bz1;
            if (mode == 4) {
                __half* oh = (__half*)out;
                if (r0 < M)
                    *(__half2*)(oh + (size_t)r0 * Nn + c0) = __floats2half2_rn(raw00, raw01);
                if (r1 < M)
                    *(__half2*)(oh + (size_t)r1 * Nn + c0) = __floats2half2_rn(raw10, raw11);
                continue;
            }
            if (mode == 3) {
                if (r0 < M) {
                    out[(size_t)r0 * Nn + c0] = raw00;
                    out[(size_t)r0 * Nn + c1] = raw01;
                }
                if (r1 < M) {
                    out[(size_t)r1 * Nn + c0] = raw10;
                    out[(size_t)r1 * Nn + c1] = raw11;
                }
                continue;
            }
            float v00 = fmaxf(raw00, 0.f);
            float v01 = fmaxf(raw01, 0.f);
            float v10 = fmaxf(raw10, 0.f);
            float v11 = fmaxf(raw11, 0.f);
            if (mode == 0) {
                float w00 = round_out ? tf32r(v00) : v00;
                float w01 = round_out ? tf32r(v01) : v01;
                float w10 = round_out ? tf32r(v10) : v10;
                float w11 = round_out ? tf32r(v11) : v11;
                if (r0 < M) {
                    out[(size_t)r0 * Nn + c0] = w00;
                    out[(size_t)r0 * Nn + c1] = w01;
                    if (out2) {
                        out2[(size_t)r0 * Nn + c0] = tf32r(v00);
                        out2[(size_t)r0 * Nn + c1] = tf32r(v01);
                    }
                }
                if (r1 < M) {
                    out[(size_t)r1 * Nn + c0] = w10;
                    out[(size_t)r1 * Nn + c1] = w11;
                    if (out2) {
                        out2[(size_t)r1 * Nn + c0] = tf32r(v10);
                        out2[(size_t)r1 * Nn + c1] = tf32r(v11);
                    }
                }
            } else if (mode == 1) {
                if (r0 < M) {
                    size_t b = (size_t)sidx[r0] * Nn;
                    red_add2(&out[b + c0], v00, v01);
                }
                if (r1 < M) {
                    size_t b = (size_t)sidx[r1] * Nn;
                    red_add2(&out[b + c0], v10, v11);
                }
            } else {
                if (r0 < M) {
                    size_t b = (size_t)r0 * Nn;
                    float w0 = fmaxf(res[b + c0] + v00, 0.f);
                    float w1 = fmaxf(res[b + c1] + v01, 0.f);
                    out[b + c0] = w0; out[b + c1] = w1;
                    if (out2) { out2[b + c0] = tf32r(w0); out2[b + c1] = tf32r(w1); }
                }
                if (r1 < M) {
                    size_t b = (size_t)r1 * Nn;
                    float w0 = fmaxf(res[b + c0] + v10, 0.f);
                    float w1 = fmaxf(res[b + c1] + v11, 0.f);
                    out[b + c0] = w0; out[b + c1] = w1;
                    if (out2) { out2[b + c0] = tf32r(w0); out2[b + c1] = tf32r(w1); }
                }
            }
        }
    }
#undef STAGE
}

// ---------------- small kernels ----------------
__global__ void count_edges(const int* __restrict__ pn, const int* __restrict__ cn,
                            float* __restrict__ cp, float* __restrict__ cc)
{
    int e = blockIdx.x * blockDim.x + threadIdx.x;
    if (e < N_EDGES) {
        atomicAdd(&cp[pn[e]], 1.f);
        atomicAdd(&cc[cn[e]], 1.f);
    }
}

__global__ void inv_counts(const float* __restrict__ c, float* __restrict__ ic, int n)
{
    int i = blockIdx.x * blockDim.x + threadIdx.x;
    if (i < n) ic[i] = 1.0f / fmaxf(c[i], 1.f);
}

__global__ void round_copy(const float* __restrict__ in, float* __restrict__ o, int n)
{
    int i = blockIdx.x * blockDim.x + threadIdx.x;
    if (i < n) o[i] = tf32r(in[i]);
}

__global__ void fill_grid(float* __restrict__ g)
{
    int i = blockIdx.x * blockDim.x + threadIdx.x;
    if (i < TABPAD) {
        int j = i > 4096 ? 4096 : i;
        g[i] = (float)j * (1.0f / 4096.0f);
    }
}

// batched transpose: dst[n*K+k] = rna(src[k*N+n]) for each job
#define NJOBS 13
struct TrJobs {
    const float* s[NJOBS];
    float*       d[NJOBS];
    int          K[NJOBS];
    int          N[NJOBS];
};

__global__ void transpose_batch(TrJobs tj)
{
    int j = blockIdx.y;
    int K = tj.K[j], N = tj.N[j];
    int i = blockIdx.x * blockDim.x + threadIdx.x;
    if (i >= K * N) return;
    int k = i / N, n = i % N;
    tj.d[j][(size_t)n * K + k] = tf32r(tj.s[j][i]);
}

// ---------------- host ----------------
extern "C" void kernel_launch(void* const* d_in, const int* in_sizes, int n_in,
                              void* d_out, int out_size)
{
    (void)in_sizes; (void)n_in; (void)out_size;
    const float* batch_token = (const float*)d_in[0];
    const int*   e_p_node    = (const int*)  d_in[1];
    const int*   e_c_node    = (const int*)  d_in[2];
    const float* e_p_ind     = (const float*)d_in[3];
    const float* e_c_ind     = (const float*)d_in[4];
    const float* p_mask      = (const float*)d_in[5];
    const float* c_mask      = (const float*)d_in[6];
    const float* start_tok   = (const float*)d_in[7];
    const float* end_tok     = (const float*)d_in[8];
    const float* Wt[20];
    for (int i = 0; i < 20; i++) Wt[i] = (const float*)d_in[9 + i];
    const float *Vw1=Wt[0],*Vb1=Wt[1],*Vw2=Wt[2],*Vb2=Wt[3];
    const float *Ew1=Wt[4],*Eb1=Wt[5],*Ew2=Wt[6],*Eb2=Wt[7];
    const float *Pw1=Wt[8],*Pb1=Wt[9],*Pw2=Wt[10],*Pb2=Wt[11];
    const float *Cw1=Wt[12],*Cb1=Wt[13],*Cw2=Wt[14],*Cb2=Wt[15];
    const float *Aw1=Wt[16],*Ab1=Wt[17],*Aw2=Wt[18],*Ab2=Wt[19];

    float *g_h, *g_h2, *g_hr, *g_nh, *g_spc, *g_cpc, *g_icpc;
    float *g_grid, *g_epT, *g_tabP, *g_tabC;
    __half *g_UVh;
    float *w_V1, *w_V2, *w_E2, *w_UV, *w_P1c, *w_C1c, *w_P2, *w_C2, *w_A1, *w_A2;
    cudaGetSymbolAddress((void**)&g_h,    d_h);
    cudaGetSymbolAddress((void**)&g_h2,   d_h2);
    cudaGetSymbolAddress((void**)&g_hr,   d_hr);
    cudaGetSymbolAddress((void**)&g_nh,   d_nh);
    cudaGetSymbolAddress((void**)&g_UVh,  d_UVh);
    cudaGetSymbolAddress((void**)&g_spc,  d_spc);
    cudaGetSymbolAddress((void**)&g_cpc,  d_cpc);
    cudaGetSymbolAddress((void**)&g_icpc, d_icpc);
    cudaGetSymbolAddress((void**)&g_grid, d_grid);
    cudaGetSymbolAddress((void**)&g_epT,  d_epT);
    cudaGetSymbolAddress((void**)&g_tabP, d_tabP);
    cudaGetSymbolAddress((void**)&g_tabC, d_tabC);
    cudaGetSymbolAddress((void**)&w_V1,   d_wV1);
    cudaGetSymbolAddress((void**)&w_V2,   d_wV2);
    cudaGetSymbolAddress((void**)&w_E2,   d_wE2);
    cudaGetSymbolAddress((void**)&w_UV,   d_wUV);
    cudaGetSymbolAddress((void**)&w_P1c,  d_wP1c);
    cudaGetSymbolAddress((void**)&w_C1c,  d_wC1c);
    cudaGetSymbolAddress((void**)&w_P2,   d_wP2);
    cudaGetSymbolAddress((void**)&w_C2,   d_wC2);
    cudaGetSymbolAddress((void**)&w_A1,   d_wA1);
    cudaGetSymbolAddress((void**)&w_A2,   d_wA2);

    float* g_sp = g_spc;
    float* g_sc = g_spc + N_NODES * D;
    float* g_cp = g_cpc;
    float* g_cc = g_cpc + N_NODES;
    float* g_icp = g_icpc;
    float* g_icc = g_icpc + N_NODES;

    cudaFuncSetAttribute(gemm_tc<128, 64>, cudaFuncAttributeMaxDynamicSharedMemorySize, SMEM_BYTES);
    cudaFuncSetAttribute(gemm_tc<64, 128>, cudaFuncAttributeMaxDynamicSharedMemorySize, SMEM_BYTES);

    cudaStream_t s = 0;
    const size_t SB = SMEM_BYTES;

    // ---- batched weight transposes ----
    TrJobs tj;
    int ji = 0;
    auto addj = [&](const float* src, float* dst, int K, int N) {
        tj.s[ji] = src; tj.d[ji] = dst; tj.K[ji] = K; tj.N[ji] = N; ji++;
    };
    addj(Vw1, w_V1, D, H1);
    addj(Pw1,              w_UV + 0 * H1 * D, D, H1);
    addj(Pw1 + D * H1,     w_UV + 1 * H1 * D, D, H1);
    addj(Cw1,              w_UV + 2 * H1 * D, D, H1);
    addj(Cw1 + D * H1,     w_UV + 3 * H1 * D, D, H1);
    addj(Pw1 + 2 * D * H1, w_P1c, D, H1);
    addj(Cw1 + 2 * D * H1, w_C1c, D, H1);
    addj(Vw2, w_V2, H1, D);
    addj(Ew2, w_E2, H1, D);
    addj(Pw2, w_P2, H1, D);
    addj(Cw2, w_C2, H1, D);
    addj(Aw2, w_A2, H1, D);
    addj(Aw1, w_A1, 3 * D, H1);
    transpose_batch<<<dim3((3 * D * H1 + 255) / 256, NJOBS), 256, 0, s>>>(tj);

    round_copy<<<(N_NODES * D + 255) / 256, 256, 0, s>>>(batch_token, g_hr, N_NODES * D);
    fill_grid<<<(TABPAD + 255) / 256, 256, 0, s>>>(g_grid);

    cudaMemsetAsync(g_cpc, 0, 2 * N_NODES * sizeof(float), s);
    count_edges<<<(N_EDGES + 255) / 256, 256, 0, s>>>(e_p_node, e_c_node, g_cp, g_cc);
    inv_counts<<<(2 * N_NODES + 255) / 256, 256, 0, s>>>(g_cpc, g_icpc, 2 * N_NODES);

#define GEMM_A(Aptr, S0, I0, S1, I1, S2, RKI, RKW, RKB, M_, K_, S01S, WT, NN, BIAS, OUT, LD, MD, SIDX, RES, RO, OUT2, X0, X1, X2) \
    gemm_tc<128, 64><<<dim3((NN) / 64, ((M_) + 127) / 128), 256, SB, s>>>(Aptr, S0, I0, S1, I1, S2, \
        RKI, RKW, RKB, M_, K_, S01S, WT, NN, BIAS, OUT, LD, MD, SIDX, RES, RO, OUT2, X0, X1, X2)
#define GEMM_B(Aptr, S0, I0, S1, I1, S2, RKI, RKW, RKB, M_, K_, S01S, WT, NN, BIAS, OUT, LD, MD, SIDX, RES, RO, OUT2, X0, X1, X2) \
    gemm_tc<64, 128><<<dim3((NN) / 128, ((M_) + 63) / 64), 256, SB, s>>>(Aptr, S0, I0, S1, I1, S2, \
        RKI, RKW, RKB, M_, K_, S01S, WT, NN, BIAS, OUT, LD, MD, SIDX, RES, RO, OUT2, X0, X1, X2)

    // ---- h0 = MLP_V(batch_token_rounded) ----
    GEMM_A(g_hr, nullptr,nullptr,nullptr,nullptr,nullptr, nullptr,nullptr,nullptr,
           N_NODES, D, 0, w_V1, H1, Vb1, g_nh, 0, 0, nullptr, nullptr, 1, nullptr,
           nullptr, nullptr, nullptr);
    GEMM_A(g_nh, nullptr,nullptr,nullptr,nullptr,nullptr, nullptr,nullptr,nullptr,
           N_NODES, H1, 0, w_V2, D, Vb2, g_h, 0, 0, nullptr, nullptr, 0, g_hr,
           nullptr, nullptr, nullptr);

    // ---- edge-MLP lookup tables on 4097 knots ----
    GEMM_A(nullptr, nullptr,nullptr,nullptr,nullptr,nullptr, g_grid, Ew1, Eb1,
           TABN, H1, 0, w_E2, D, Eb2, g_epT, 2, 0, nullptr, nullptr, 1, nullptr,
           nullptr, nullptr, nullptr);
    GEMM_A(g_epT, nullptr,nullptr,nullptr,nullptr,nullptr, nullptr,nullptr,nullptr,
           TABN, D, 0, w_P1c, H1, Pb1, g_tabP, 0, 3, nullptr, nullptr, 0, nullptr,
           nullptr, nullptr, nullptr);
    GEMM_A(g_epT, nullptr,nullptr,nullptr,nullptr,nullptr, nullptr,nullptr,nullptr,
           TABN, D, 0, w_C1c, H1, Cb1, g_tabC, 0, 3, nullptr, nullptr, 0, nullptr,
           nullptr, nullptr, nullptr);

    // ---- hops ----
    float* hin  = g_h;
    float* hout = g_h2;
    for (int hop = 0; hop < 3; hop++) {
        cudaMemsetAsync(g_spc, 0, (size_t)2 * N_NODES * D * sizeof(float), s);

        // UV = h @ [P1a|P1b|C1a|C1b] -> [50k, 1024] fp16
        GEMM_A(g_hr, nullptr,nullptr,nullptr,nullptr,nullptr, nullptr,nullptr,nullptr,
               N_NODES, D, 0, w_UV, 4 * H1, nullptr, (float*)g_UVh, 0, 4, nullptr, nullptr, 0, nullptr,
               nullptr, nullptr, nullptr);

        // P layer2 (SUM3T + v2-red scatter)
        GEMM_B(g_tabP, (const float*)(g_UVh + 0), e_c_node,
               (const float*)(g_UVh + H1), e_p_node, nullptr,
               e_p_ind, nullptr, nullptr,
               N_EDGES, H1, 4 * H1, w_P2, D, Pb2, g_sp, 3, 1, e_p_node, nullptr, 0, nullptr,
               nullptr, nullptr, nullptr);

        // C layer2
        GEMM_B(g_tabC, (const float*)(g_UVh + 2 * H1), e_p_node,
               (const float*)(g_UVh + 3 * H1), e_c_node, nullptr,
               e_c_ind, nullptr, nullptr,
               N_EDGES, H1, 4 * H1, w_C2, D, Cb2, g_sc, 3, 1, e_c_node, nullptr, 0, nullptr,
               nullptr, nullptr, nullptr);

        // aggregator layer1 with fused finalize (loader 4)
        GEMM_A(nullptr, g_hr, nullptr, g_sp, nullptr, g_sc,
               g_icp, start_tok, end_tok,
               N_NODES, 3 * D, 0, w_A1, H1, Ab1, g_nh, 4, 0, nullptr, nullptr, 1, nullptr,
               p_mask, c_mask, g_icc);
        float* hdst = (hop == 2) ? (float*)d_out : hout;
        GEMM_A(g_nh, nullptr,nullptr,nullptr,nullptr,nullptr, nullptr,nullptr,nullptr,
               N_NODES, H1, 0, w_A2, D, Ab2, hdst, 0, 2, nullptr, hin, 0, g_hr,
               nullptr, nullptr, nullptr);

        float* tmp = hin;
        hin  = hdst;
        hout = tmp;
    }
#undef GEMM_A
#undef GEMM_B
}

// round 16
// speedup vs baseline: 1.2405x; 1.0317x over previous
#include <cuda_runtime.h>
#include <cuda_fp16.h>
#include <cstdint>
#include <cstddef>

#define N_NODES 50000
#define N_EDGES 500000
#define D 128
#define H1 256
#define TABN 4097
#define TABPAD 4104

#define BK 32
#define ALD 36
#define BLD 36
#define STAGES 3
#define SMEM_BYTES (STAGES * (128 + 64) * 36 * 4)

// ---------------- scratch ----------------
__device__ float d_h  [N_NODES * D];
__device__ float d_h2 [N_NODES * D];
__device__ float d_hr [N_NODES * D];
__device__ float d_nh [N_NODES * H1];
__device__ __half d_UVh[(size_t)N_NODES * 4 * H1]; // [50k,1024] fp16: UP|VP|UC|VC
__device__ float d_spc[2 * N_NODES * D];           // sp | sc contiguous
__device__ float d_cpc[2 * N_NODES];               // cp | cc contiguous
__device__ float d_grid[TABPAD];
__device__ float d_epT [TABPAD * D];
__device__ __half d_tabP[TABPAD * H1];             // fp16 lerp tables (incl bias)
__device__ __half d_tabC[TABPAD * H1];
// transposed + tf32-rounded weights ([N][K])
__device__ float d_wV1[D * H1];
__device__ float d_wV2[H1 * D];
__device__ float d_wE2[H1 * D];
__device__ float d_wUV[4 * H1 * D];
__device__ float d_wP1c[H1 * D];
__device__ float d_wC1c[H1 * D];
__device__ float d_wP2[H1 * D];
__device__ float d_wC2[H1 * D];
__device__ float d_wA1[3 * D * H1];
__device__ float d_wA2[H1 * D];

// ---------------- helpers ----------------
__device__ __forceinline__ float tf32r(float v) {
    uint32_t r;
    asm("cvt.rna.tf32.f32 %0, %1;" : "=r"(r) : "f"(v));
    return __uint_as_float(r);
}

__device__ __forceinline__ float4 h4f(uint2 r) {
    __half2 a = *reinterpret_cast<__half2*>(&r.x);
    __half2 b = *reinterpret_cast<__half2*>(&r.y);
    float2 fa = __half22float2(a), fb = __half22float2(b);
    return make_float4(fa.x, fa.y, fb.x, fb.y);
}

__device__ __forceinline__ void red_add2(float* p, float a, float b) {
    asm volatile("red.global.add.v2.f32 [%0], {%1, %2};"
                 :: "l"(p), "f"(a), "f"(b) : "memory");
}

__device__ __forceinline__ void mma_tf32(float c[4],
                                         uint32_t a0, uint32_t a1, uint32_t a2, uint32_t a3,
                                         uint32_t b0, uint32_t b1) {
    asm volatile(
        "mma.sync.aligned.m16n8k8.row.col.f32.tf32.tf32.f32 "
        "{%0,%1,%2,%3}, {%4,%5,%6,%7}, {%8,%9}, {%0,%1,%2,%3};"
        : "+f"(c[0]), "+f"(c[1]), "+f"(c[2]), "+f"(c[3])
        : "r"(a0), "r"(a1), "r"(a2), "r"(a3), "r"(b0), "r"(b1));
}

__device__ __forceinline__ void ldsm4(uint32_t& r0, uint32_t& r1, uint32_t& r2, uint32_t& r3,
                                      const float* p) {
    uint32_t a = (uint32_t)__cvta_generic_to_shared(p);
    asm volatile("ldmatrix.sync.aligned.m8n8.x4.shared.b16 {%0,%1,%2,%3}, [%4];"
                 : "=r"(r0), "=r"(r1), "=r"(r2), "=r"(r3) : "r"(a));
}

__device__ __forceinline__ void cp16(float* sm, const float* gm, bool pred) {
    uint32_t sa = (uint32_t)__cvta_generic_to_shared(sm);
    int sz = pred ? 16 : 0;
    asm volatile("cp.async.cg.shared.global [%0], [%1], 16, %2;\n"
                 :: "r"(sa), "l"(gm), "r"(sz));
}

// ---------------- unified tf32 GEMM, templated block tile ----------------
// <TBM, TBN> in {<128,64>, <64,128>}; 256 threads; warp tile 32x32.
// Wt is TRANSPOSED-ROUNDED [Nn][K].
// loader: 0 DIRECT, 1 CAT3(K=384), 2 RANK1,
//         3 SUM3T (fp16 gathers + FP16 lerp table rows of 256 via A)
// mode: 0 relu-store(+round/out2), 1 vector-red scatter relu, 2 residual,
//       3 raw fp32 store, 4 raw fp16 store
template<int TBM, int TBN>
__global__ __launch_bounds__(256) void gemm_tc(
    const float* __restrict__ A,
    const float* __restrict__ s0, const int* __restrict__ i0,
    const float* __restrict__ s1, const int* __restrict__ i1,
    const float* __restrict__ s2,
    const float* __restrict__ rk_ind, const float* __restrict__ rk_w1,
    const float* __restrict__ rk_b1,
    int M, int K, int s01s,
    const float* __restrict__ Wt, int Nn,
    const float* __restrict__ bias,
    float* __restrict__ out,
    int loader, int mode, const int* __restrict__ sidx,
    const float* __restrict__ res,
    int round_out, float* __restrict__ out2)
{
    constexpr int AIT = TBM / 32;
    constexpr int BIT = TBN / 32;
    constexpr int ASZ = TBM * ALD;
    constexpr int BSZ = TBN * BLD;
    constexpr int STG = ASZ + BSZ;
    constexpr int WGM = TBM / 32;

    extern __shared__ float smem[];

    const int tid  = threadIdx.x;
    const int lane = tid & 31;
    const int wid  = tid >> 5;
    const int wm   = (wid % WGM) * 32;
    const int wn   = (wid / WGM) * 32;
    const int bm   = blockIdx.y * TBM;
    const int bn   = blockIdx.x * TBN;

    const int akq = (tid & 7) * 4;
    int arow[AIT]; bool aval[AIT]; int rr0[AIT], rr1[AIT], trow[AIT]; float aind[AIT];
#pragma unroll
    for (int it = 0; it < AIT; ++it) {
        int r  = it * 32 + (tid >> 3);
        int gr = bm + r;
        aval[it] = (gr < M);
        int g = aval[it] ? gr : 0;
        arow[it] = g;
        trow[it] = 0;
        if (loader == 1 || loader == 3) {
            rr0[it] = i0 ? i0[g] : g;
            rr1[it] = i1 ? i1[g] : g;
        }
        if (loader == 2) {
            aind[it] = aval[it] ? __ldg(rk_ind + g) : 0.f;
        } else if (loader == 3) {
            float x = (aval[it] ? __ldg(rk_ind + g) : 0.f) * 4096.0f;
            int tr = (int)x;
            if (tr > 4095) tr = 4095;
            trow[it] = tr;
            aind[it] = x - (float)tr;
        }
    }
    const int bkq = (tid & 7) * 4;
    const int bn0 = tid >> 3;

    float acc[2][4][4] = {};
    const int KT = K / BK;

#define STAGE(k0, buf)                                                           \
    do {                                                                         \
        float* Ab = (buf);                                                       \
        float* Bb = (buf) + ASZ;                                                 \
        if (loader == 2) {                                                       \
            float4 w  = *(const float4*)(rk_w1 + (k0) + akq);                    \
            float4 bb = *(const float4*)(rk_b1 + (k0) + akq);                    \
            _Pragma("unroll")                                                    \
            for (int it = 0; it < AIT; ++it) {                                   \
                int r = it * 32 + (tid >> 3);                                    \
                float4 v;                                                        \
                v.x = tf32r(fmaxf(fmaf(aind[it], w.x, bb.x), 0.f));              \
                v.y = tf32r(fmaxf(fmaf(aind[it], w.y, bb.y), 0.f));              \
                v.z = tf32r(fmaxf(fmaf(aind[it], w.z, bb.z), 0.f));              \
                v.w = tf32r(fmaxf(fmaf(aind[it], w.w, bb.w), 0.f));              \
                *(float4*)&Ab[r * ALD + akq] = v;                                \
            }                                                                    \
        } else if (loader == 3) {                                                \
            uint2 ru[AIT], rv[AIT], rt0[AIT], rt1[AIT];                          \
            const __half* h0 = (const __half*)s0;                                \
            const __half* h1 = (const __half*)s1;                                \
            const __half* ht = (const __half*)A;                                 \
            _Pragma("unroll")                                                    \
            for (int it = 0; it < AIT; ++it)                                     \
                ru[it] = *(const uint2*)(h0 + (size_t)rr0[it] * s01s + (k0) + akq); \
            _Pragma("unroll")                                                    \
            for (int it = 0; it < AIT; ++it)                                     \
                rv[it] = *(const uint2*)(h1 + (size_t)rr1[it] * s01s + (k0) + akq); \
            _Pragma("unroll")                                                    \
            for (int it = 0; it < AIT; ++it) {                                   \
                const __half* tb = ht + (size_t)trow[it] * 256 + (k0) + akq;     \
                rt0[it] = *(const uint2*)tb;                                     \
                rt1[it] = *(const uint2*)(tb + 256);                             \
            }                                                                    \
            _Pragma("unroll")                                                    \
            for (int it = 0; it < AIT; ++it) {                                   \
                int r = it * 32 + (tid >> 3);                                    \
                float fr = aind[it];                                             \
                float4 u  = h4f(ru[it]);                                         \
                float4 v  = h4f(rv[it]);                                         \
                float4 t0 = h4f(rt0[it]);                                        \
                float4 t1 = h4f(rt1[it]);                                        \
                float4 o;                                                        \
                o.x = tf32r(fmaxf(u.x + v.x + t0.x + fr * (t1.x - t0.x), 0.f));  \
                o.y = tf32r(fmaxf(u.y + v.y + t0.y + fr * (t1.y - t0.y), 0.f));  \
                o.z = tf32r(fmaxf(u.z + v.z + t0.z + fr * (t1.z - t0.z), 0.f));  \
                o.w = tf32r(fmaxf(u.w + v.w + t0.w + fr * (t1.w - t0.w), 0.f));  \
                *(float4*)&Ab[r * ALD + akq] = o;                                \
            }                                                                    \
        } else {                                                                 \
            _Pragma("unroll")                                                    \
            for (int it = 0; it < AIT; ++it) {                                   \
                int r = it * 32 + (tid >> 3);                                    \
                const float* src;                                                \
                if (loader == 1) {                                               \
                    int seg  = (k0) >> 7;                                        \
                    int koff = ((k0) & 127) + akq;                               \
                    src = (seg == 0) ? s0 + (size_t)rr0[it] * 128 + koff         \
                        : (seg == 1) ? s1 + (size_t)rr1[it] * 128 + koff         \
                        :              s2 + (size_t)arow[it] * 128 + koff;       \
                } else {                                                         \
                    src = A + (size_t)arow[it] * K + (k0) + akq;                 \
                }                                                                \
                cp16(&Ab[r * ALD + akq], src, aval[it]);                         \
            }                                                                    \
        }                                                                        \
        _Pragma("unroll")                                                        \
        for (int it = 0; it < BIT; ++it) {                                       \
            int n = bn0 + it * 32;                                               \
            cp16(&Bb[n * BLD + bkq],                                             \
                 Wt + (size_t)(bn + n) * K + (k0) + bkq, true);                  \
        }                                                                        \
    } while (0)

    STAGE(0, smem);
    asm volatile("cp.async.commit_group;\n" ::: "memory");
    if (KT > 1) STAGE(BK, smem + STG);
    asm volatile("cp.async.commit_group;\n" ::: "memory");

    const int a_row = wm + ((lane >> 3) & 1) * 8 + (lane & 7);
    const int a_col = (lane >> 4) * 4;
    const int b_row = wn + (lane >> 4) * 8 + (lane & 7);
    const int b_col = ((lane >> 3) & 1) * 4;

    for (int t = 0; t < KT; ++t) {
        asm volatile("cp.async.wait_group 1;\n" ::: "memory");
        __syncthreads();

        const float* Ab = smem + (t % STAGES) * STG;
        const float* Bb = Ab + ASZ;
#pragma unroll
        for (int ks = 0; ks < 4; ++ks) {
            const int k = ks * 8;
            uint32_t a[2][4], b[4][2];
#pragma unroll
            for (int mi = 0; mi < 2; ++mi)
                ldsm4(a[mi][0], a[mi][1], a[mi][2], a[mi][3],
                      &Ab[(a_row + mi * 16) * ALD + a_col + k]);
#pragma unroll
            for (int nip = 0; nip < 2; ++nip)
                ldsm4(b[nip * 2][0], b[nip * 2][1], b[nip * 2 + 1][0], b[nip * 2 + 1][1],
                      &Bb[(b_row + nip * 16) * BLD + b_col + k]);
#pragma unroll
            for (int ni = 0; ni < 4; ++ni)
#pragma unroll
                for (int mi = 0; mi < 2; ++mi)
                    mma_tf32(acc[mi][ni], a[mi][0], a[mi][1], a[mi][2], a[mi][3],
                             b[ni][0], b[ni][1]);
        }
        __syncthreads();
        if (t + 2 < KT) STAGE((t + 2) * BK, smem + ((t + 2) % STAGES) * STG);
        asm volatile("cp.async.commit_group;\n" ::: "memory");
    }

    // ---------------- epilogue (warp tile 32x32) ----------------
#pragma unroll
    for (int mi = 0; mi < 2; ++mi) {
        int r0 = bm + wm + mi * 16 + (lane >> 2);
        int r1 = r0 + 8;
#pragma unroll
        for (int ni = 0; ni < 4; ++ni) {
            int c0 = bn + wn + ni * 8 + (lane & 3) * 2;
            int c1 = c0 + 1;
            float bz0 = bias ? bias[c0] : 0.f;
            float bz1 = bias ? bias[c1] : 0.f;
            float raw00 = acc[mi][ni][0] + bz0;
            float raw01 = acc[mi][ni][1] + bz1;
            float raw10 = acc[mi][ni][2] + bz0;
            float raw11 = acc[mi][ni][3] + bz1;
            if (mode == 4) {
                __half* oh = (__half*)out;
                if (r0 < M)
                    *(__half2*)(oh + (size_t)r0 * Nn + c0) = __floats2half2_rn(raw00, raw01);
                if (r1 < M)
                    *(__half2*)(oh + (size_t)r1 * Nn + c0) = __floats2half2_rn(raw10, raw11);
                continue;
            }
            if (mode == 3) {
                if (r0 < M) {
                    out[(size_t)r0 * Nn + c0] = raw00;
                    out[(size_t)r0 * Nn + c1] = raw01;
                }
                if (r1 < M) {
                    out[(size_t)r1 * Nn + c0] = raw10;
                    out[(size_t)r1 * Nn + c1] = raw11;
                }
                continue;
            }
            float v00 = fmaxf(raw00, 0.f);
            float v01 = fmaxf(raw01, 0.f);
            float v10 = fmaxf(raw10, 0.f);
            float v11 = fmaxf(raw11, 0.f);
            if (mode == 0) {
                float w00 = round_out ? tf32r(v00) : v00;
                float w01 = round_out ? tf32r(v01) : v01;
                float w10 = round_out ? tf32r(v10) : v10;
                float w11 = round_out ? tf32r(v11) : v11;
                if (r0 < M) {
                    out[(size_t)r0 * Nn + c0] = w00;
                    out[(size_t)r0 * Nn + c1] = w01;
                    if (out2) {
                        out2[(size_t)r0 * Nn + c0] = tf32r(v00);
                        out2[(size_t)r0 * Nn + c1] = tf32r(v01);
                    }
                }
                if (r1 < M) {
                    out[(size_t)r1 * Nn + c0] = w10;
                    out[(size_t)r1 * Nn + c1] = w11;
                    if (out2) {
                        out2[(size_t)r1 * Nn + c0] = tf32r(v10);
                        out2[(size_t)r1 * Nn + c1] = tf32r(v11);
                    }
                }
            } else if (mode == 1) {
                if (r0 < M) {
                    size_t b = (size_t)sidx[r0] * Nn;
                    red_add2(&out[b + c0], v00, v01);
                }
                if (r1 < M) {
                    size_t b = (size_t)sidx[r1] * Nn;
                    red_add2(&out[b + c0], v10, v11);
                }
            } else {
                if (r0 < M) {
                    size_t b = (size_t)r0 * Nn;
                    float w0 = fmaxf(res[b + c0] + v00, 0.f);
                    float w1 = fmaxf(res[b + c1] + v01, 0.f);
                    out[b + c0] = w0; out[b + c1] = w1;
                    if (out2) { out2[b + c0] = tf32r(w0); out2[b + c1] = tf32r(w1); }
                }
                if (r1 < M) {
                    size_t b = (size_t)r1 * Nn;
                    float w0 = fmaxf(res[b + c0] + v10, 0.f);
                    float w1 = fmaxf(res[b + c1] + v11, 0.f);
                    out[b + c0] = w0; out[b + c1] = w1;
                    if (out2) { out2[b + c0] = tf32r(w0); out2[b + c1] = tf32r(w1); }
                }
            }
        }
    }
#undef STAGE
}

// ---------------- small kernels ----------------
__global__ void count_edges(const int* __restrict__ pn, const int* __restrict__ cn,
                            float* __restrict__ cp, float* __restrict__ cc)
{
    int e = blockIdx.x * blockDim.x + threadIdx.x;
    if (e < N_EDGES) {
        atomicAdd(&cp[pn[e]], 1.f);
        atomicAdd(&cc[cn[e]], 1.f);
    }
}

__global__ void finalize_s(float* __restrict__ sp, float* __restrict__ sc,
                           const float* __restrict__ cp, const float* __restrict__ cc,
                           const float* __restrict__ pm, const float* __restrict__ cm,
                           const float* __restrict__ st, const float* __restrict__ et)
{
    int i = blockIdx.x * blockDim.x + threadIdx.x;
    if (i >= N_NODES * D) return;
    int n = i >> 7, d = i & 127;
    sp[i] = tf32r(sp[i] / fmaxf(cp[n], 1.f) + pm[n] * st[d]);
    sc[i] = tf32r(sc[i] / fmaxf(cc[n], 1.f) + cm[n] * et[d]);
}

__global__ void round_copy(const float* __restrict__ in, float* __restrict__ o, int n)
{
    int i = blockIdx.x * blockDim.x + threadIdx.x;
    if (i < n) o[i] = tf32r(in[i]);
}

__global__ void fill_grid(float* __restrict__ g)
{
    int i = blockIdx.x * blockDim.x + threadIdx.x;
    if (i < TABPAD) {
        int j = i > 4096 ? 4096 : i;
        g[i] = (float)j * (1.0f / 4096.0f);
    }
}

// batched transpose: dst[n*K+k] = rna(src[k*N+n]) for each job
#define NJOBS 13
struct TrJobs {
    const float* s[NJOBS];
    float*       d[NJOBS];
    int          K[NJOBS];
    int          N[NJOBS];
};

__global__ void transpose_batch(TrJobs tj)
{
    int j = blockIdx.y;
    int K = tj.K[j], N = tj.N[j];
    int i = blockIdx.x * blockDim.x + threadIdx.x;
    if (i >= K * N) return;
    int k = i / N, n = i % N;
    tj.d[j][(size_t)n * K + k] = tf32r(tj.s[j][i]);
}

// ---------------- host ----------------
extern "C" void kernel_launch(void* const* d_in, const int* in_sizes, int n_in,
                              void* d_out, int out_size)
{
    (void)in_sizes; (void)n_in; (void)out_size;
    const float* batch_token = (const float*)d_in[0];
    const int*   e_p_node    = (const int*)  d_in[1];
    const int*   e_c_node    = (const int*)  d_in[2];
    const float* e_p_ind     = (const float*)d_in[3];
    const float* e_c_ind     = (const float*)d_in[4];
    const float* p_mask      = (const float*)d_in[5];
    const float* c_mask      = (const float*)d_in[6];
    const float* start_tok   = (const float*)d_in[7];
    const float* end_tok     = (const float*)d_in[8];
    const float* Wt[20];
    for (int i = 0; i < 20; i++) Wt[i] = (const float*)d_in[9 + i];
    const float *Vw1=Wt[0],*Vb1=Wt[1],*Vw2=Wt[2],*Vb2=Wt[3];
    const float *Ew1=Wt[4],*Eb1=Wt[5],*Ew2=Wt[6],*Eb2=Wt[7];
    const float *Pw1=Wt[8],*Pb1=Wt[9],*Pw2=Wt[10],*Pb2=Wt[11];
    const float *Cw1=Wt[12],*Cb1=Wt[13],*Cw2=Wt[14],*Cb2=Wt[15];
    const float *Aw1=Wt[16],*Ab1=Wt[17],*Aw2=Wt[18],*Ab2=Wt[19];

    float *g_h, *g_h2, *g_hr, *g_nh, *g_spc, *g_cpc;
    float *g_grid, *g_epT;
    __half *g_UVh, *g_tabP, *g_tabC;
    float *w_V1, *w_V2, *w_E2, *w_UV, *w_P1c, *w_C1c, *w_P2, *w_C2, *w_A1, *w_A2;
    cudaGetSymbolAddress((void**)&g_h,    d_h);
    cudaGetSymbolAddress((void**)&g_h2,   d_h2);
    cudaGetSymbolAddress((void**)&g_hr,   d_hr);
    cudaGetSymbolAddress((void**)&g_nh,   d_nh);
    cudaGetSymbolAddress((void**)&g_UVh,  d_UVh);
    cudaGetSymbolAddress((void**)&g_spc,  d_spc);
    cudaGetSymbolAddress((void**)&g_cpc,  d_cpc);
    cudaGetSymbolAddress((void**)&g_grid, d_grid);
    cudaGetSymbolAddress((void**)&g_epT,  d_epT);
    cudaGetSymbolAddress((void**)&g_tabP, d_tabP);
    cudaGetSymbolAddress((void**)&g_tabC, d_tabC);
    cudaGetSymbolAddress((void**)&w_V1,   d_wV1);
    cudaGetSymbolAddress((void**)&w_V2,   d_wV2);
    cudaGetSymbolAddress((void**)&w_E2,   d_wE2);
    cudaGetSymbolAddress((void**)&w_UV,   d_wUV);
    cudaGetSymbolAddress((void**)&w_P1c,  d_wP1c);
    cudaGetSymbolAddress((void**)&w_C1c,  d_wC1c);
    cudaGetSymbolAddress((void**)&w_P2,   d_wP2);
    cudaGetSymbolAddress((void**)&w_C2,   d_wC2);
    cudaGetSymbolAddress((void**)&w_A1,   d_wA1);
    cudaGetSymbolAddress((void**)&w_A2,   d_wA2);

    float* g_sp = g_spc;
    float* g_sc = g_spc + N_NODES * D;
    float* g_cp = g_cpc;
    float* g_cc = g_cpc + N_NODES;

    cudaFuncSetAttribute(gemm_tc<128, 64>, cudaFuncAttributeMaxDynamicSharedMemorySize, SMEM_BYTES);
    cudaFuncSetAttribute(gemm_tc<64, 128>, cudaFuncAttributeMaxDynamicSharedMemorySize, SMEM_BYTES);

    cudaStream_t s = 0;
    const size_t SB = SMEM_BYTES;

    // ---- batched weight transposes ----
    TrJobs tj;
    int ji = 0;
    auto addj = [&](const float* src, float* dst, int K, int N) {
        tj.s[ji] = src; tj.d[ji] = dst; tj.K[ji] = K; tj.N[ji] = N; ji++;
    };
    addj(Vw1, w_V1, D, H1);
    addj(Pw1,              w_UV + 0 * H1 * D, D, H1);
    addj(Pw1 + D * H1,     w_UV + 1 * H1 * D, D, H1);
    addj(Cw1,              w_UV + 2 * H1 * D, D, H1);
    addj(Cw1 + D * H1,     w_UV + 3 * H1 * D, D, H1);
    addj(Pw1 + 2 * D * H1, w_P1c, D, H1);
    addj(Cw1 + 2 * D * H1, w_C1c, D, H1);
    addj(Vw2, w_V2, H1, D);
    addj(Ew2, w_E2, H1, D);
    addj(Pw2, w_P2, H1, D);
    addj(Cw2, w_C2, H1, D);
    addj(Aw2, w_A2, H1, D);
    addj(Aw1, w_A1, 3 * D, H1);
    transpose_batch<<<dim3((3 * D * H1 + 255) / 256, NJOBS), 256, 0, s>>>(tj);

    round_copy<<<(N_NODES * D + 255) / 256, 256, 0, s>>>(batch_token, g_hr, N_NODES * D);
    fill_grid<<<(TABPAD + 255) / 256, 256, 0, s>>>(g_grid);

    cudaMemsetAsync(g_cpc, 0, 2 * N_NODES * sizeof(float), s);
    count_edges<<<(N_EDGES + 255) / 256, 256, 0, s>>>(e_p_node, e_c_node, g_cp, g_cc);

#define GEMM_A(Aptr, S0, I0, S1, I1, S2, RKI, RKW, RKB, M_, K_, S01S, WT, NN, BIAS, OUT, LD, MD, SIDX, RES, RO, OUT2) \
    gemm_tc<128, 64><<<dim3((NN) / 64, ((M_) + 127) / 128), 256, SB, s>>>(Aptr, S0, I0, S1, I1, S2, \
        RKI, RKW, RKB, M_, K_, S01S, WT, NN, BIAS, OUT, LD, MD, SIDX, RES, RO, OUT2)
#define GEMM_B(Aptr, S0, I0, S1, I1, S2, RKI, RKW, RKB, M_, K_, S01S, WT, NN, BIAS, OUT, LD, MD, SIDX, RES, RO, OUT2) \
    gemm_tc<64, 128><<<dim3((NN) / 128, ((M_) + 63) / 64), 256, SB, s>>>(Aptr, S0, I0, S1, I1, S2, \
        RKI, RKW, RKB, M_, K_, S01S, WT, NN, BIAS, OUT, LD, MD, SIDX, RES, RO, OUT2)

    // ---- h0 = MLP_V(batch_token_rounded) ----
    GEMM_A(g_hr, nullptr,nullptr,nullptr,nullptr,nullptr, nullptr,nullptr,nullptr,
           N_NODES, D, 0, w_V1, H1, Vb1, g_nh, 0, 0, nullptr, nullptr, 1, nullptr);
    GEMM_A(g_nh, nullptr,nullptr,nullptr,nullptr,nullptr, nullptr,nullptr,nullptr,
           N_NODES, H1, 0, w_V2, D, Vb2, g_h, 0, 0, nullptr, nullptr, 0, g_hr);

    // ---- edge-MLP lookup tables on 4097 knots (fp16 output, mode 4) ----
    GEMM_A(nullptr, nullptr,nullptr,nullptr,nullptr,nullptr, g_grid, Ew1, Eb1,
           TABN, H1, 0, w_E2, D, Eb2, g_epT, 2, 0, nullptr, nullptr, 1, nullptr);
    GEMM_A(g_epT, nullptr,nullptr,nullptr,nullptr,nullptr, nullptr,nullptr,nullptr,
           TABN, D, 0, w_P1c, H1, Pb1, (float*)g_tabP, 0, 4, nullptr, nullptr, 0, nullptr);
    GEMM_A(g_epT, nullptr,nullptr,nullptr,nullptr,nullptr, nullptr,nullptr,nullptr,
           TABN, D, 0, w_C1c, H1, Cb1, (float*)g_tabC, 0, 4, nullptr, nullptr, 0, nullptr);

    // ---- hops ----
    float* hin  = g_h;
    float* hout = g_h2;
    for (int hop = 0; hop < 3; hop++) {
        cudaMemsetAsync(g_spc, 0, (size_t)2 * N_NODES * D * sizeof(float), s);

        // UV = h @ [P1a|P1b|C1a|C1b] -> [50k, 1024] fp16
        GEMM_A(g_hr, nullptr,nullptr,nullptr,nullptr,nullptr, nullptr,nullptr,nullptr,
               N_NODES, D, 0, w_UV, 4 * H1, nullptr, (float*)g_UVh, 0, 4, nullptr, nullptr, 0, nullptr);

        // P layer2 (SUM3T, fp16 table, v2-red scatter)
        GEMM_B((const float*)g_tabP, (const float*)(g_UVh + 0), e_c_node,
               (const float*)(g_UVh + H1), e_p_node, nullptr,
               e_p_ind, nullptr, nullptr,
               N_EDGES, H1, 4 * H1, w_P2, D, Pb2, g_sp, 3, 1, e_p_node, nullptr, 0, nullptr);

        // C layer2
        GEMM_B((const float*)g_tabC, (const float*)(g_UVh + 2 * H1), e_p_node,
               (const float*)(g_UVh + 3 * H1), e_c_node, nullptr,
               e_c_ind, nullptr, nullptr,
               N_EDGES, H1, 4 * H1, w_C2, D, Cb2, g_sc, 3, 1, e_c_node, nullptr, 0, nullptr);

        finalize_s<<<(N_NODES * D + 255) / 256, 256, 0, s>>>(
            g_sp, g_sc, g_cp, g_cc, p_mask, c_mask, start_tok, end_tok);

        // aggregator
        GEMM_A(nullptr, g_hr, nullptr, g_sp, nullptr, g_sc, nullptr,nullptr,nullptr,
               N_NODES, 3 * D, 0, w_A1, H1, Ab1, g_nh, 1, 0, nullptr, nullptr, 1, nullptr);
        float* hdst = (hop == 2) ? (float*)d_out : hout;
        GEMM_A(g_nh, nullptr,nullptr,nullptr,nullptr,nullptr, nullptr,nullptr,nullptr,
               N_NODES, H1, 0, w_A2, D, Ab2, hdst, 0, 2, nullptr, hin, 0, g_hr);

        float* tmp = hin;
        hin  = hdst;
        hout = tmp;
    }
#undef GEMM_A
#undef GEMM_B
}